// round 13
// baseline (speedup 1.0000x reference)
#include <cuda_runtime.h>
#include <cuda_fp16.h>
#include <cstdint>

#define HID   2048
#define INTER 10944
#define INTP  11008          // padded: 86*128, 172*64
#define TTOK  4096
#define EPS   1e-6f

#define BK 64                // fp16 elems per k-chunk = 128B swizzled row

// ---- kernel A (q/o/down): BM=64, BN=128, 128 threads (2x2 warps, 32x64 tiles) ----
#define A64_BY  (64*128)                 // 8 KB
#define B64_BY  (128*128)                // 16 KB
#define STAGE_M (A64_BY + B64_BY)        // 24 KB
#define SMEM_M  (2*STAGE_M)              // 48 KB -> 4 CTAs/SM

// ---- kernel B (fused gate/up): BM=128, BN=64 per weight ----
#define FA_BY  (128*128)                 // 16 KB
#define FB_BY  (64*128)                  // 8 KB each weight
#define STAGE_F (FA_BY + 2*FB_BY)        // 32 KB
#define SMEM_F (2*STAGE_F)               // 64 KB -> 3 CTAs/SM

// ---------------- scratch ----------------
__device__ __half g_xn[(size_t)TTOK * HID];
__device__ __half g_q[(size_t)TTOK * HID];
__device__ float  g_hidden[(size_t)TTOK * HID];
__device__ __half g_act[(size_t)TTOK * INTP];
__device__ __half g_wq[(size_t)HID * HID];
__device__ __half g_wo[(size_t)HID * HID];
__device__ __half g_wg[(size_t)INTP * HID];
__device__ __half g_wu[(size_t)INTP * HID];
__device__ __half g_wd[(size_t)HID * INTP];

// ---------------- PTX helpers ----------------
__device__ __forceinline__ uint32_t smem_u32(const void* p) {
    uint32_t a;
    asm("{ .reg .u64 t; cvta.to.shared.u64 t, %1; cvt.u32.u64 %0, t; }" : "=r"(a) : "l"(p));
    return a;
}
#define SWZ(off) ((off) ^ (((off) >> 3) & 0x70))

__device__ __forceinline__ void cp16(uint32_t smem_dst, const void* gsrc) {
    asm volatile("cp.async.cg.shared.global [%0], [%1], 16;" :: "r"(smem_dst), "l"(gsrc));
}
#define CP_COMMIT  asm volatile("cp.async.commit_group;" ::: "memory")
#define CP_WAIT(n) asm volatile("cp.async.wait_group %0;" :: "n"(n) : "memory")

__device__ __forceinline__ void ldsm_x4(uint32_t r[4], uint32_t saddr) {
    asm volatile("ldmatrix.sync.aligned.m8n8.x4.shared.b16 {%0,%1,%2,%3}, [%4];"
        : "=r"(r[0]), "=r"(r[1]), "=r"(r[2]), "=r"(r[3]) : "r"(saddr));
}

__device__ __forceinline__ void mma16816(float c[4], const uint32_t a[4],
                                         uint32_t b0, uint32_t b1) {
    asm volatile(
        "mma.sync.aligned.m16n8k16.row.col.f32.f16.f16.f32 "
        "{%0,%1,%2,%3}, {%4,%5,%6,%7}, {%8,%9}, {%0,%1,%2,%3};"
        : "+f"(c[0]), "+f"(c[1]), "+f"(c[2]), "+f"(c[3])
        : "r"(a[0]), "r"(a[1]), "r"(a[2]), "r"(a[3]), "r"(b0), "r"(b1));
}

// ================= kernel A: C[M,N] = A[M,K] @ B[N,K]^T =================
// BM=64, BN=128: 128 threads, warps 2(M) x 2(N), warp tile 32x64, 4 CTAs/SM.
// EPI 0: fp16 -> Ch.   EPI 1: fp32 acc + Res -> Cf.
template <int EPI>
__global__ void __launch_bounds__(128, 4)
gemm_m64(const __half* __restrict__ A, const __half* __restrict__ B,
         const float* __restrict__ Res, __half* __restrict__ Ch,
         float* __restrict__ Cf, int K, int N) {
    extern __shared__ char smem[];
    const uint32_t sb = smem_u32(smem);
    const int tid = threadIdx.x, warp = tid >> 5, lane = tid & 31;
    const int wm = warp & 1, wn = warp >> 1;
    const int m0 = blockIdx.x * 64, n0 = blockIdx.y * 128;
    const int nkb = K / BK;

    const __half* Ag = A + (size_t)m0 * K;
    const __half* Bg = B + (size_t)n0 * K;
    auto issue = [&](int kb) {
        const uint32_t base = sb + (kb & 1) * STAGE_M;
        const int koff = kb * BK;
        #pragma unroll
        for (int i = 0; i < 12; i++) {
            const int c = tid + i * 128;
            if (c < 512) {
                const int r = c >> 3, cc = c & 7;
                cp16(base + SWZ((uint32_t)(r * 128 + cc * 16)),
                     Ag + (size_t)r * K + koff + cc * 8);
            } else {
                const int idx = c - 512, r = idx >> 3, cc = idx & 7;
                cp16(base + A64_BY + SWZ((uint32_t)(r * 128 + cc * 16)),
                     Bg + (size_t)r * K + koff + cc * 8);
            }
        }
    };

    const int frow = (lane & 7) | (((lane >> 3) & 1) << 3);
    const int fg = lane >> 4, fx = frow & 7;
    uint32_t arow[2], brow[4];
    #pragma unroll
    for (int mi = 0; mi < 2; mi++) arow[mi] = (uint32_t)((wm * 32 + mi * 16 + frow) * 128);
    #pragma unroll
    for (int nj = 0; nj < 4; nj++) brow[nj] = (uint32_t)(A64_BY + (wn * 64 + nj * 16 + frow) * 128);

    float acc[2][8][4];
    #pragma unroll
    for (int mi = 0; mi < 2; mi++)
        #pragma unroll
        for (int j = 0; j < 8; j++)
            #pragma unroll
            for (int r = 0; r < 4; r++) acc[mi][j][r] = 0.0f;

    issue(0); CP_COMMIT;

    for (int kb = 0; kb < nkb; ++kb) {
        if (kb + 1 < nkb) { issue(kb + 1); CP_COMMIT; CP_WAIT(1); }
        else              { CP_WAIT(0); }
        __syncthreads();

        const uint32_t base = sb + (kb & 1) * STAGE_M;
        #pragma unroll
        for (int ks = 0; ks < 4; ks++) {
            const uint32_t colx = (uint32_t)(((2 * ks + fg) ^ fx) << 4);
            uint32_t a[2][4], b[4][4];
            #pragma unroll
            for (int mi = 0; mi < 2; mi++) ldsm_x4(a[mi], base + arow[mi] + colx);
            #pragma unroll
            for (int nj = 0; nj < 4; nj++) ldsm_x4(b[nj], base + brow[nj] + colx);
            #pragma unroll
            for (int mi = 0; mi < 2; mi++)
                #pragma unroll
                for (int nj = 0; nj < 4; nj++) {
                    mma16816(acc[mi][2 * nj + 0], a[mi], b[nj][0], b[nj][2]);
                    mma16816(acc[mi][2 * nj + 1], a[mi], b[nj][1], b[nj][3]);
                }
        }
        __syncthreads();   // 2-stage ring
    }

    const int rb = m0 + wm * 32 + (lane >> 2);
    const int cb = n0 + wn * 64 + (lane & 3) * 2;
    #pragma unroll
    for (int mi = 0; mi < 2; mi++) {
        #pragma unroll
        for (int j = 0; j < 8; j++) {
            const int r0 = rb + mi * 16;
            const int c  = cb + j * 8;
            if (EPI == 0) {
                *(__half2*)(Ch + (size_t)r0 * N + c) =
                    __floats2half2_rn(acc[mi][j][0], acc[mi][j][1]);
                *(__half2*)(Ch + (size_t)(r0 + 8) * N + c) =
                    __floats2half2_rn(acc[mi][j][2], acc[mi][j][3]);
            } else {
                float2 v0 = *(const float2*)(Res + (size_t)r0 * N + c);
                float2 v1 = *(const float2*)(Res + (size_t)(r0 + 8) * N + c);
                v0.x += acc[mi][j][0]; v0.y += acc[mi][j][1];
                v1.x += acc[mi][j][2]; v1.y += acc[mi][j][3];
                *(float2*)(Cf + (size_t)r0 * N + c)       = v0;
                *(float2*)(Cf + (size_t)(r0 + 8) * N + c) = v1;
            }
        }
    }
}

// ======= kernel B: fused gate/up + silu.  act = silu(A@Wg^T) * (A@Wu^T) =======
// 128 threads, warps 2x2, BN=64 per weight, warp tile 64x32 per weight, 3 CTAs/SM.
__global__ void __launch_bounds__(128, 3)
gemm_gateup(const __half* __restrict__ A, const __half* __restrict__ Wg,
            const __half* __restrict__ Wu, __half* __restrict__ act, int K) {
    extern __shared__ char smem[];
    const uint32_t sb = smem_u32(smem);
    const int tid = threadIdx.x, warp = tid >> 5, lane = tid & 31;
    const int wm = warp & 1, wn = warp >> 1;
    const int m0 = blockIdx.x * 128, n0 = blockIdx.y * 64;
    const int nkb = K / BK;

    const __half* Ag = A  + (size_t)m0 * K;
    const __half* Gg = Wg + (size_t)n0 * K;
    const __half* Ug = Wu + (size_t)n0 * K;
    auto issue = [&](int kb) {
        const uint32_t base = sb + (kb & 1) * STAGE_F;
        const int koff = kb * BK;
        #pragma unroll
        for (int i = 0; i < 16; i++) {
            const int c = tid + i * 128;
            if (c < 1024) {
                const int r = c >> 3, cc = c & 7;
                cp16(base + SWZ((uint32_t)(r * 128 + cc * 16)),
                     Ag + (size_t)r * K + koff + cc * 8);
            } else if (c < 1536) {
                const int idx = c - 1024, r = idx >> 3, cc = idx & 7;
                cp16(base + FA_BY + SWZ((uint32_t)(r * 128 + cc * 16)),
                     Gg + (size_t)r * K + koff + cc * 8);
            } else {
                const int idx = c - 1536, r = idx >> 3, cc = idx & 7;
                cp16(base + FA_BY + FB_BY + SWZ((uint32_t)(r * 128 + cc * 16)),
                     Ug + (size_t)r * K + koff + cc * 8);
            }
        }
    };

    const int frow = (lane & 7) | (((lane >> 3) & 1) << 3);
    const int fg = lane >> 4, fx = frow & 7;
    uint32_t arow[4], grow[2], urow[2];
    #pragma unroll
    for (int mi = 0; mi < 4; mi++) arow[mi] = (uint32_t)((wm * 64 + mi * 16 + frow) * 128);
    #pragma unroll
    for (int nj = 0; nj < 2; nj++) {
        grow[nj] = (uint32_t)(FA_BY         + (wn * 32 + nj * 16 + frow) * 128);
        urow[nj] = (uint32_t)(FA_BY + FB_BY + (wn * 32 + nj * 16 + frow) * 128);
    }

    float ag[4][4][4], au[4][4][4];
    #pragma unroll
    for (int mi = 0; mi < 4; mi++)
        #pragma unroll
        for (int j = 0; j < 4; j++)
            #pragma unroll
            for (int r = 0; r < 4; r++) { ag[mi][j][r] = 0.0f; au[mi][j][r] = 0.0f; }

    issue(0); CP_COMMIT;

    for (int kb = 0; kb < nkb; ++kb) {
        if (kb + 1 < nkb) { issue(kb + 1); CP_COMMIT; CP_WAIT(1); }
        else              { CP_WAIT(0); }
        __syncthreads();

        const uint32_t base = sb + (kb & 1) * STAGE_F;
        #pragma unroll
        for (int ks = 0; ks < 4; ks++) {
            const uint32_t colx = (uint32_t)(((2 * ks + fg) ^ fx) << 4);
            uint32_t a[4][4], bg[2][4], bu[2][4];
            #pragma unroll
            for (int mi = 0; mi < 4; mi++) ldsm_x4(a[mi], base + arow[mi] + colx);
            #pragma unroll
            for (int nj = 0; nj < 2; nj++) {
                ldsm_x4(bg[nj], base + grow[nj] + colx);
                ldsm_x4(bu[nj], base + urow[nj] + colx);
            }
            #pragma unroll
            for (int mi = 0; mi < 4; mi++)
                #pragma unroll
                for (int nj = 0; nj < 2; nj++) {
                    mma16816(ag[mi][2 * nj + 0], a[mi], bg[nj][0], bg[nj][2]);
                    mma16816(ag[mi][2 * nj + 1], a[mi], bg[nj][1], bg[nj][3]);
                    mma16816(au[mi][2 * nj + 0], a[mi], bu[nj][0], bu[nj][2]);
                    mma16816(au[mi][2 * nj + 1], a[mi], bu[nj][1], bu[nj][3]);
                }
        }
        __syncthreads();
    }

    const int rb = m0 + wm * 64 + (lane >> 2);
    const int cb = n0 + wn * 32 + (lane & 3) * 2;
    #pragma unroll
    for (int mi = 0; mi < 4; mi++) {
        #pragma unroll
        for (int j = 0; j < 4; j++) {
            const int r0 = rb + mi * 16;
            const int c  = cb + j * 8;
            float g0 = ag[mi][j][0], g1 = ag[mi][j][1], g2 = ag[mi][j][2], g3 = ag[mi][j][3];
            float v0 = g0 / (1.0f + __expf(-g0)) * au[mi][j][0];
            float v1 = g1 / (1.0f + __expf(-g1)) * au[mi][j][1];
            float v2 = g2 / (1.0f + __expf(-g2)) * au[mi][j][2];
            float v3 = g3 / (1.0f + __expf(-g3)) * au[mi][j][3];
            *(__half2*)(act + (size_t)r0 * INTP + c)       = __floats2half2_rn(v0, v1);
            *(__half2*)(act + (size_t)(r0 + 8) * INTP + c) = __floats2half2_rn(v2, v3);
        }
    }
}

// ---------------- fp32 -> fp16 weight convert with padding ----------------
__global__ void cvt_pad(const float* __restrict__ in, __half* __restrict__ out,
                        int ro, int co, int ri, int ci) {
    const size_t i = (size_t)blockIdx.x * blockDim.x + threadIdx.x;
    const size_t n4 = ((size_t)ro * co) >> 2;
    if (i >= n4) return;
    const int cw = co >> 2;
    const int r = (int)(i / cw);
    const int c = (int)(i - (size_t)r * cw) * 4;
    __half2 h0 = __floats2half2_rn(0.f, 0.f), h1 = h0;
    if (r < ri && c < ci) {
        float4 v = *(const float4*)(in + (size_t)r * ci + c);
        h0 = __floats2half2_rn(v.x, v.y);
        h1 = __floats2half2_rn(v.z, v.w);
    }
    __half2* d = (__half2*)(out + (size_t)r * co + c);
    d[0] = h0; d[1] = h1;
}

// ---------------- rmsnorm -> fp16 ----------------
__global__ void rmsnorm_h(const float* __restrict__ x, const float* __restrict__ w,
                          __half* __restrict__ out) {
    const int row = blockIdx.x, t = threadIdx.x;
    const float4* xv = (const float4*)(x + (size_t)row * HID);
    const float4* wv = (const float4*)w;
    float4 a = xv[t], b = xv[t + 256];
    float ss = a.x*a.x + a.y*a.y + a.z*a.z + a.w*a.w
             + b.x*b.x + b.y*b.y + b.z*b.z + b.w*b.w;
    __shared__ float red[8];
    #pragma unroll
    for (int o = 16; o; o >>= 1) ss += __shfl_xor_sync(0xffffffffu, ss, o);
    if ((t & 31) == 0) red[t >> 5] = ss;
    __syncthreads();
    float tot = red[0]+red[1]+red[2]+red[3]+red[4]+red[5]+red[6]+red[7];
    const float sc = rsqrtf(tot * (1.0f / HID) + EPS);
    float4 wa = wv[t], wb = wv[t + 256];
    __half2* ov = (__half2*)(out + (size_t)row * HID);
    ov[2*t]   = __floats2half2_rn(a.x*sc*wa.x, a.y*sc*wa.y);
    ov[2*t+1] = __floats2half2_rn(a.z*sc*wa.z, a.w*sc*wa.w);
    ov[2*(t+256)]   = __floats2half2_rn(b.x*sc*wb.x, b.y*sc*wb.y);
    ov[2*(t+256)+1] = __floats2half2_rn(b.z*sc*wb.z, b.w*sc*wb.w);
}

// ---------------- launcher ----------------
extern "C" void kernel_launch(void* const* d_in, const int* in_sizes, int n_in,
                              void* d_out, int out_size) {
    const float* x      = (const float*)d_in[0];
    const float* in_w   = (const float*)d_in[2];
    const float* post_w = (const float*)d_in[3];
    const float* Wq     = (const float*)d_in[4];
    const float* Wo     = (const float*)d_in[5];
    const float* Wg     = (const float*)d_in[6];
    const float* Wu     = (const float*)d_in[7];
    const float* Wd     = (const float*)d_in[8];
    float* out = (float*)d_out;
    const int T = in_sizes[0] / HID;  // 4096

    __half *xn, *q, *act, *wq, *wo, *wg, *wu, *wd;
    float* hidden;
    cudaGetSymbolAddress((void**)&xn, g_xn);
    cudaGetSymbolAddress((void**)&q, g_q);
    cudaGetSymbolAddress((void**)&hidden, g_hidden);
    cudaGetSymbolAddress((void**)&act, g_act);
    cudaGetSymbolAddress((void**)&wq, g_wq);
    cudaGetSymbolAddress((void**)&wo, g_wo);
    cudaGetSymbolAddress((void**)&wg, g_wg);
    cudaGetSymbolAddress((void**)&wu, g_wu);
    cudaGetSymbolAddress((void**)&wd, g_wd);

    cudaFuncSetAttribute(gemm_m64<0>, cudaFuncAttributeMaxDynamicSharedMemorySize, SMEM_M);
    cudaFuncSetAttribute(gemm_m64<1>, cudaFuncAttributeMaxDynamicSharedMemorySize, SMEM_M);
    cudaFuncSetAttribute(gemm_gateup, cudaFuncAttributeMaxDynamicSharedMemorySize, SMEM_F);

    // weight conversion (fp32 -> fp16, padded for INTER)
    {
        auto launch_cvt = [&](const float* src, __half* dst, int ro, int co, int ri, int ci) {
            size_t n4 = ((size_t)ro * co) >> 2;
            cvt_pad<<<(unsigned)((n4 + 255) / 256), 256>>>(src, dst, ro, co, ri, ci);
        };
        launch_cvt(Wq, wq, HID, HID, HID, HID);
        launch_cvt(Wo, wo, HID, HID, HID, HID);
        launch_cvt(Wg, wg, INTP, HID, INTER, HID);
        launch_cvt(Wu, wu, INTP, HID, INTER, HID);
        launch_cvt(Wd, wd, HID, INTP, HID, INTER);
    }

    const dim3 gridH64(T / 64, HID / 128);   // (64, 16) = 1024 CTAs
    const dim3 gridF(T / 128, INTP / 64);    // (32, 172)

    // 1. input_layernorm -> fp16
    rmsnorm_h<<<T, 256>>>(x, in_w, xn);
    // 2. q = xn @ Wq^T (fp16)
    gemm_m64<0><<<gridH64, 128, SMEM_M>>>(xn, wq, nullptr, q, nullptr, HID, HID);
    // 3. hidden = x + q @ Wo^T (fp32)
    gemm_m64<1><<<gridH64, 128, SMEM_M>>>(q, wo, x, nullptr, hidden, HID, HID);
    // 4. post_attention_layernorm -> fp16
    rmsnorm_h<<<T, 256>>>(hidden, post_w, xn);
    // 5. act = silu(xn@Wg^T) * (xn@Wu^T)   (fused, fp16, padded N)
    gemm_gateup<<<gridF, 128, SMEM_F>>>(xn, wg, wu, act, HID);
    // 6. out = hidden + act @ Wd^T (fp32)
    gemm_m64<1><<<gridH64, 128, SMEM_M>>>(act, wd, hidden, nullptr, out, INTP, HID);
}

// round 14
// speedup vs baseline: 1.5009x; 1.5009x over previous
#include <cuda_runtime.h>
#include <cuda_fp16.h>
#include <cstdint>

#define HID   2048
#define INTER 10944
#define INTP  11008          // padded: 86*128, 172*64
#define TTOK  4096
#define EPS   1e-6f

#define BK 64                // fp16 elems per k-chunk = 128B swizzled row

// ---- split-K GEMM (q/o/down): BM=128, BN=128, 128 threads (2x2 warps, 64x64 tiles) ----
#define A_BY   (128*128)                 // 16 KB
#define B_BY   (128*128)                 // 16 KB
#define STAGE_A (A_BY + B_BY)            // 32 KB
#define SMEM_A (2*STAGE_A)               // 64 KB -> 3 CTAs/SM

// ---- fused gate/up: BM=128, BN=64 per weight ----
#define FA_BY  (128*128)                 // 16 KB
#define FB_BY  (64*128)                  // 8 KB each weight
#define STAGE_F (FA_BY + 2*FB_BY)        // 32 KB
#define SMEM_F (2*STAGE_F)               // 64 KB -> 3 CTAs/SM

// ---------------- scratch ----------------
__device__ float  g_part[2 * (size_t)TTOK * HID];   // split-K partials (64 MB)
__device__ __half g_xn[(size_t)TTOK * HID];
__device__ __half g_q[(size_t)TTOK * HID];
__device__ float  g_hidden[(size_t)TTOK * HID];
__device__ __half g_act[(size_t)TTOK * INTP];
__device__ __half g_wq[(size_t)HID * HID];
__device__ __half g_wo[(size_t)HID * HID];
__device__ __half g_wg[(size_t)INTP * HID];
__device__ __half g_wu[(size_t)INTP * HID];
__device__ __half g_wd[(size_t)HID * INTP];

// ---------------- PTX helpers ----------------
__device__ __forceinline__ uint32_t smem_u32(const void* p) {
    uint32_t a;
    asm("{ .reg .u64 t; cvta.to.shared.u64 t, %1; cvt.u32.u64 %0, t; }" : "=r"(a) : "l"(p));
    return a;
}
#define SWZ(off) ((off) ^ (((off) >> 3) & 0x70))

__device__ __forceinline__ void cp16(uint32_t smem_dst, const void* gsrc) {
    asm volatile("cp.async.cg.shared.global [%0], [%1], 16;" :: "r"(smem_dst), "l"(gsrc));
}
#define CP_COMMIT  asm volatile("cp.async.commit_group;" ::: "memory")
#define CP_WAIT(n) asm volatile("cp.async.wait_group %0;" :: "n"(n) : "memory")

__device__ __forceinline__ void ldsm_x4(uint32_t r[4], uint32_t saddr) {
    asm volatile("ldmatrix.sync.aligned.m8n8.x4.shared.b16 {%0,%1,%2,%3}, [%4];"
        : "=r"(r[0]), "=r"(r[1]), "=r"(r[2]), "=r"(r[3]) : "r"(saddr));
}

__device__ __forceinline__ void mma16816(float c[4], const uint32_t a[4],
                                         uint32_t b0, uint32_t b1) {
    asm volatile(
        "mma.sync.aligned.m16n8k16.row.col.f32.f16.f16.f32 "
        "{%0,%1,%2,%3}, {%4,%5,%6,%7}, {%8,%9}, {%0,%1,%2,%3};"
        : "+f"(c[0]), "+f"(c[1]), "+f"(c[2]), "+f"(c[3])
        : "r"(a[0]), "r"(a[1]), "r"(a[2]), "r"(a[3]), "r"(b0), "r"(b1));
}

// ============ split-K GEMM: P[kz] = A[:, kz*K/2 : (kz+1)*K/2] @ B^T slice ============
// BM=128, BN=128, warps 2x2, warp tile 64x64, 3 CTAs/SM. blockIdx.z = kz (0/1).
// Writes raw fp32 partial to P + kz*M*N.
__global__ void __launch_bounds__(128, 3)
gemm_split(const __half* __restrict__ A, const __half* __restrict__ B,
           float* __restrict__ P, int K, int N) {
    extern __shared__ char smem[];
    const uint32_t sb = smem_u32(smem);
    const int tid = threadIdx.x, warp = tid >> 5, lane = tid & 31;
    const int wm = warp & 1, wn = warp >> 1;
    const int m0 = blockIdx.x * 128, n0 = blockIdx.y * 128;
    const int kz = blockIdx.z;
    const int Kh = K >> 1;
    const int nkb = Kh / BK;
    float* Cf = P + (size_t)kz * ((size_t)gridDim.x * 128) * N;

    const __half* Ag = A + (size_t)m0 * K + (size_t)kz * Kh;
    const __half* Bg = B + (size_t)n0 * K + (size_t)kz * Kh;
    auto issue = [&](int kb) {
        const uint32_t base = sb + (kb & 1) * STAGE_A;
        const int koff = kb * BK;
        #pragma unroll
        for (int i = 0; i < 16; i++) {
            const int c = tid + i * 128;
            const int idx = c & 1023, r = idx >> 3, cc = idx & 7;
            const uint32_t so = SWZ((uint32_t)(r * 128 + cc * 16));
            const size_t go = (size_t)r * K + koff + cc * 8;
            if (c < 1024) cp16(base + so,         Ag + go);
            else          cp16(base + A_BY + so,  Bg + go);
        }
    };

    const int frow = (lane & 7) | (((lane >> 3) & 1) << 3);
    const int fg = lane >> 4, fx = frow & 7;
    uint32_t arow[4], brow[4];
    #pragma unroll
    for (int mi = 0; mi < 4; mi++) arow[mi] = (uint32_t)((wm * 64 + mi * 16 + frow) * 128);
    #pragma unroll
    for (int nj = 0; nj < 4; nj++) brow[nj] = (uint32_t)(A_BY + (wn * 64 + nj * 16 + frow) * 128);

    float acc[4][8][4];
    #pragma unroll
    for (int mi = 0; mi < 4; mi++)
        #pragma unroll
        for (int j = 0; j < 8; j++)
            #pragma unroll
            for (int r = 0; r < 4; r++) acc[mi][j][r] = 0.0f;

    issue(0); CP_COMMIT;

    for (int kb = 0; kb < nkb; ++kb) {
        if (kb + 1 < nkb) { issue(kb + 1); CP_COMMIT; CP_WAIT(1); }
        else              { CP_WAIT(0); }
        __syncthreads();

        const uint32_t base = sb + (kb & 1) * STAGE_A;
        #pragma unroll
        for (int ks = 0; ks < 4; ks++) {
            const uint32_t colx = (uint32_t)(((2 * ks + fg) ^ fx) << 4);
            uint32_t a[4][4], b[4][4];
            #pragma unroll
            for (int mi = 0; mi < 4; mi++) ldsm_x4(a[mi], base + arow[mi] + colx);
            #pragma unroll
            for (int nj = 0; nj < 4; nj++) ldsm_x4(b[nj], base + brow[nj] + colx);
            #pragma unroll
            for (int mi = 0; mi < 4; mi++)
                #pragma unroll
                for (int nj = 0; nj < 4; nj++) {
                    mma16816(acc[mi][2 * nj + 0], a[mi], b[nj][0], b[nj][2]);
                    mma16816(acc[mi][2 * nj + 1], a[mi], b[nj][1], b[nj][3]);
                }
        }
        __syncthreads();   // 2-stage ring
    }

    const int rb = m0 + wm * 64 + (lane >> 2);
    const int cb = n0 + wn * 64 + (lane & 3) * 2;
    #pragma unroll
    for (int mi = 0; mi < 4; mi++) {
        #pragma unroll
        for (int j = 0; j < 8; j++) {
            const int r0 = rb + mi * 16;
            const int c  = cb + j * 8;
            *(float2*)(Cf + (size_t)r0 * N + c) =
                make_float2(acc[mi][j][0], acc[mi][j][1]);
            *(float2*)(Cf + (size_t)(r0 + 8) * N + c) =
                make_float2(acc[mi][j][2], acc[mi][j][3]);
        }
    }
}

// ======= fused gate/up + silu.  act = silu(A@Wg^T) * (A@Wu^T) =======
__global__ void __launch_bounds__(128, 3)
gemm_gateup(const __half* __restrict__ A, const __half* __restrict__ Wg,
            const __half* __restrict__ Wu, __half* __restrict__ act, int K) {
    extern __shared__ char smem[];
    const uint32_t sb = smem_u32(smem);
    const int tid = threadIdx.x, warp = tid >> 5, lane = tid & 31;
    const int wm = warp & 1, wn = warp >> 1;
    const int m0 = blockIdx.x * 128, n0 = blockIdx.y * 64;
    const int nkb = K / BK;

    const __half* Ag = A  + (size_t)m0 * K;
    const __half* Gg = Wg + (size_t)n0 * K;
    const __half* Ug = Wu + (size_t)n0 * K;
    auto issue = [&](int kb) {
        const uint32_t base = sb + (kb & 1) * STAGE_F;
        const int koff = kb * BK;
        #pragma unroll
        for (int i = 0; i < 16; i++) {
            const int c = tid + i * 128;
            if (c < 1024) {
                const int r = c >> 3, cc = c & 7;
                cp16(base + SWZ((uint32_t)(r * 128 + cc * 16)),
                     Ag + (size_t)r * K + koff + cc * 8);
            } else if (c < 1536) {
                const int idx = c - 1024, r = idx >> 3, cc = idx & 7;
                cp16(base + FA_BY + SWZ((uint32_t)(r * 128 + cc * 16)),
                     Gg + (size_t)r * K + koff + cc * 8);
            } else {
                const int idx = c - 1536, r = idx >> 3, cc = idx & 7;
                cp16(base + FA_BY + FB_BY + SWZ((uint32_t)(r * 128 + cc * 16)),
                     Ug + (size_t)r * K + koff + cc * 8);
            }
        }
    };

    const int frow = (lane & 7) | (((lane >> 3) & 1) << 3);
    const int fg = lane >> 4, fx = frow & 7;
    uint32_t arow[4], grow[2], urow[2];
    #pragma unroll
    for (int mi = 0; mi < 4; mi++) arow[mi] = (uint32_t)((wm * 64 + mi * 16 + frow) * 128);
    #pragma unroll
    for (int nj = 0; nj < 2; nj++) {
        grow[nj] = (uint32_t)(FA_BY         + (wn * 32 + nj * 16 + frow) * 128);
        urow[nj] = (uint32_t)(FA_BY + FB_BY + (wn * 32 + nj * 16 + frow) * 128);
    }

    float ag[4][4][4], au[4][4][4];
    #pragma unroll
    for (int mi = 0; mi < 4; mi++)
        #pragma unroll
        for (int j = 0; j < 4; j++)
            #pragma unroll
            for (int r = 0; r < 4; r++) { ag[mi][j][r] = 0.0f; au[mi][j][r] = 0.0f; }

    issue(0); CP_COMMIT;

    for (int kb = 0; kb < nkb; ++kb) {
        if (kb + 1 < nkb) { issue(kb + 1); CP_COMMIT; CP_WAIT(1); }
        else              { CP_WAIT(0); }
        __syncthreads();

        const uint32_t base = sb + (kb & 1) * STAGE_F;
        #pragma unroll
        for (int ks = 0; ks < 4; ks++) {
            const uint32_t colx = (uint32_t)(((2 * ks + fg) ^ fx) << 4);
            uint32_t a[4][4], bg[2][4], bu[2][4];
            #pragma unroll
            for (int mi = 0; mi < 4; mi++) ldsm_x4(a[mi], base + arow[mi] + colx);
            #pragma unroll
            for (int nj = 0; nj < 2; nj++) {
                ldsm_x4(bg[nj], base + grow[nj] + colx);
                ldsm_x4(bu[nj], base + urow[nj] + colx);
            }
            #pragma unroll
            for (int mi = 0; mi < 4; mi++)
                #pragma unroll
                for (int nj = 0; nj < 2; nj++) {
                    mma16816(ag[mi][2 * nj + 0], a[mi], bg[nj][0], bg[nj][2]);
                    mma16816(ag[mi][2 * nj + 1], a[mi], bg[nj][1], bg[nj][3]);
                    mma16816(au[mi][2 * nj + 0], a[mi], bu[nj][0], bu[nj][2]);
                    mma16816(au[mi][2 * nj + 1], a[mi], bu[nj][1], bu[nj][3]);
                }
        }
        __syncthreads();
    }

    const int rb = m0 + wm * 64 + (lane >> 2);
    const int cb = n0 + wn * 32 + (lane & 3) * 2;
    #pragma unroll
    for (int mi = 0; mi < 4; mi++) {
        #pragma unroll
        for (int j = 0; j < 4; j++) {
            const int r0 = rb + mi * 16;
            const int c  = cb + j * 8;
            float g0 = ag[mi][j][0], g1 = ag[mi][j][1], g2 = ag[mi][j][2], g3 = ag[mi][j][3];
            float v0 = g0 / (1.0f + __expf(-g0)) * au[mi][j][0];
            float v1 = g1 / (1.0f + __expf(-g1)) * au[mi][j][1];
            float v2 = g2 / (1.0f + __expf(-g2)) * au[mi][j][2];
            float v3 = g3 / (1.0f + __expf(-g3)) * au[mi][j][3];
            *(__half2*)(act + (size_t)r0 * INTP + c)       = __floats2half2_rn(v0, v1);
            *(__half2*)(act + (size_t)(r0 + 8) * INTP + c) = __floats2half2_rn(v2, v3);
        }
    }
}

// ---------------- reduce kernels (deterministic fixed-order sums) ----------------
// q = fp16(p0 + p1)
__global__ void reduce_q(const float* __restrict__ p, __half* __restrict__ q, size_t n4) {
    const size_t i = (size_t)blockIdx.x * blockDim.x + threadIdx.x;
    if (i >= n4) return;
    const float4 a = ((const float4*)p)[i];
    const float4 b = ((const float4*)(p + (size_t)TTOK * HID))[i];
    __half2* d = (__half2*)q + 2 * i;
    d[0] = __floats2half2_rn(a.x + b.x, a.y + b.y);
    d[1] = __floats2half2_rn(a.z + b.z, a.w + b.w);
}

// hidden = x + p0 + p1;  xn = fp16(rmsnorm(hidden) * w)   (fused o-reduce + post-LN)
__global__ void reduce_res_norm(const float* __restrict__ p, const float* __restrict__ x,
                                const float* __restrict__ w, float* __restrict__ hidden,
                                __half* __restrict__ xn) {
    const int row = blockIdx.x, t = threadIdx.x;
    const size_t off = (size_t)row * HID;
    const float4* xv = (const float4*)(x + off);
    const float4* p0 = (const float4*)(p + off);
    const float4* p1 = (const float4*)(p + (size_t)TTOK * HID + off);
    float4 h0 = xv[t], h1 = xv[t + 256];
    {
        float4 a = p0[t], b = p1[t];
        h0.x += a.x + b.x; h0.y += a.y + b.y; h0.z += a.z + b.z; h0.w += a.w + b.w;
        a = p0[t + 256]; b = p1[t + 256];
        h1.x += a.x + b.x; h1.y += a.y + b.y; h1.z += a.z + b.z; h1.w += a.w + b.w;
    }
    float4* hv = (float4*)(hidden + off);
    hv[t] = h0; hv[t + 256] = h1;

    float ss = h0.x*h0.x + h0.y*h0.y + h0.z*h0.z + h0.w*h0.w
             + h1.x*h1.x + h1.y*h1.y + h1.z*h1.z + h1.w*h1.w;
    __shared__ float red[8];
    #pragma unroll
    for (int o = 16; o; o >>= 1) ss += __shfl_xor_sync(0xffffffffu, ss, o);
    if ((t & 31) == 0) red[t >> 5] = ss;
    __syncthreads();
    float tot = red[0]+red[1]+red[2]+red[3]+red[4]+red[5]+red[6]+red[7];
    const float sc = rsqrtf(tot * (1.0f / HID) + EPS);
    const float4* wv = (const float4*)w;
    float4 wa = wv[t], wb = wv[t + 256];
    __half2* ov = (__half2*)(xn + off);
    ov[2*t]   = __floats2half2_rn(h0.x*sc*wa.x, h0.y*sc*wa.y);
    ov[2*t+1] = __floats2half2_rn(h0.z*sc*wa.z, h0.w*sc*wa.w);
    ov[2*(t+256)]   = __floats2half2_rn(h1.x*sc*wb.x, h1.y*sc*wb.y);
    ov[2*(t+256)+1] = __floats2half2_rn(h1.z*sc*wb.z, h1.w*sc*wb.w);
}

// out = hidden + p0 + p1
__global__ void reduce_res_out(const float* __restrict__ p, const float* __restrict__ hidden,
                               float* __restrict__ out, size_t n4) {
    const size_t i = (size_t)blockIdx.x * blockDim.x + threadIdx.x;
    if (i >= n4) return;
    float4 h = ((const float4*)hidden)[i];
    const float4 a = ((const float4*)p)[i];
    const float4 b = ((const float4*)(p + (size_t)TTOK * HID))[i];
    h.x += a.x + b.x; h.y += a.y + b.y; h.z += a.z + b.z; h.w += a.w + b.w;
    ((float4*)out)[i] = h;
}

// ---------------- fp32 -> fp16 weight convert with padding ----------------
__global__ void cvt_pad(const float* __restrict__ in, __half* __restrict__ out,
                        int ro, int co, int ri, int ci) {
    const size_t i = (size_t)blockIdx.x * blockDim.x + threadIdx.x;
    const size_t n4 = ((size_t)ro * co) >> 2;
    if (i >= n4) return;
    const int cw = co >> 2;
    const int r = (int)(i / cw);
    const int c = (int)(i - (size_t)r * cw) * 4;
    __half2 h0 = __floats2half2_rn(0.f, 0.f), h1 = h0;
    if (r < ri && c < ci) {
        float4 v = *(const float4*)(in + (size_t)r * ci + c);
        h0 = __floats2half2_rn(v.x, v.y);
        h1 = __floats2half2_rn(v.z, v.w);
    }
    __half2* d = (__half2*)(out + (size_t)r * co + c);
    d[0] = h0; d[1] = h1;
}

// ---------------- rmsnorm -> fp16 ----------------
__global__ void rmsnorm_h(const float* __restrict__ x, const float* __restrict__ w,
                          __half* __restrict__ out) {
    const int row = blockIdx.x, t = threadIdx.x;
    const float4* xv = (const float4*)(x + (size_t)row * HID);
    const float4* wv = (const float4*)w;
    float4 a = xv[t], b = xv[t + 256];
    float ss = a.x*a.x + a.y*a.y + a.z*a.z + a.w*a.w
             + b.x*b.x + b.y*b.y + b.z*b.z + b.w*b.w;
    __shared__ float red[8];
    #pragma unroll
    for (int o = 16; o; o >>= 1) ss += __shfl_xor_sync(0xffffffffu, ss, o);
    if ((t & 31) == 0) red[t >> 5] = ss;
    __syncthreads();
    float tot = red[0]+red[1]+red[2]+red[3]+red[4]+red[5]+red[6]+red[7];
    const float sc = rsqrtf(tot * (1.0f / HID) + EPS);
    float4 wa = wv[t], wb = wv[t + 256];
    __half2* ov = (__half2*)(out + (size_t)row * HID);
    ov[2*t]   = __floats2half2_rn(a.x*sc*wa.x, a.y*sc*wa.y);
    ov[2*t+1] = __floats2half2_rn(a.z*sc*wa.z, a.w*sc*wa.w);
    ov[2*(t+256)]   = __floats2half2_rn(b.x*sc*wb.x, b.y*sc*wb.y);
    ov[2*(t+256)+1] = __floats2half2_rn(b.z*sc*wb.z, b.w*sc*wb.w);
}

// ---------------- launcher ----------------
extern "C" void kernel_launch(void* const* d_in, const int* in_sizes, int n_in,
                              void* d_out, int out_size) {
    const float* x      = (const float*)d_in[0];
    const float* in_w   = (const float*)d_in[2];
    const float* post_w = (const float*)d_in[3];
    const float* Wq     = (const float*)d_in[4];
    const float* Wo     = (const float*)d_in[5];
    const float* Wg     = (const float*)d_in[6];
    const float* Wu     = (const float*)d_in[7];
    const float* Wd     = (const float*)d_in[8];
    float* out = (float*)d_out;
    const int T = in_sizes[0] / HID;  // 4096

    __half *xn, *q, *act, *wq, *wo, *wg, *wu, *wd;
    float *hidden, *part;
    cudaGetSymbolAddress((void**)&xn, g_xn);
    cudaGetSymbolAddress((void**)&q, g_q);
    cudaGetSymbolAddress((void**)&hidden, g_hidden);
    cudaGetSymbolAddress((void**)&act, g_act);
    cudaGetSymbolAddress((void**)&part, g_part);
    cudaGetSymbolAddress((void**)&wq, g_wq);
    cudaGetSymbolAddress((void**)&wo, g_wo);
    cudaGetSymbolAddress((void**)&wg, g_wg);
    cudaGetSymbolAddress((void**)&wu, g_wu);
    cudaGetSymbolAddress((void**)&wd, g_wd);

    cudaFuncSetAttribute(gemm_split, cudaFuncAttributeMaxDynamicSharedMemorySize, SMEM_A);
    cudaFuncSetAttribute(gemm_gateup, cudaFuncAttributeMaxDynamicSharedMemorySize, SMEM_F);

    // weight conversion (fp32 -> fp16, padded for INTER)
    {
        auto launch_cvt = [&](const float* src, __half* dst, int ro, int co, int ri, int ci) {
            size_t n4 = ((size_t)ro * co) >> 2;
            cvt_pad<<<(unsigned)((n4 + 255) / 256), 256>>>(src, dst, ro, co, ri, ci);
        };
        launch_cvt(Wq, wq, HID, HID, HID, HID);
        launch_cvt(Wo, wo, HID, HID, HID, HID);
        launch_cvt(Wg, wg, INTP, HID, INTER, HID);
        launch_cvt(Wu, wu, INTP, HID, INTER, HID);
        launch_cvt(Wd, wd, HID, INTP, HID, INTER);
    }

    const dim3 gridS(T / 128, HID / 128, 2);   // (32, 16, 2) = 1024 CTAs
    const dim3 gridF(T / 128, INTP / 64);      // (32, 172)
    const size_t n4h = (size_t)T * HID / 4;
    const unsigned rblk = (unsigned)((n4h + 255) / 256);

    // 1. input_layernorm -> fp16
    rmsnorm_h<<<T, 256>>>(x, in_w, xn);
    // 2. q partials = xn @ Wq^T (split-K), then q = fp16(p0+p1)
    gemm_split<<<gridS, 128, SMEM_A>>>(xn, wq, part, HID, HID);
    reduce_q<<<rblk, 256>>>(part, q, n4h);
    // 3. o partials = q @ Wo^T (split-K); hidden = x + p; xn = postLN(hidden)
    gemm_split<<<gridS, 128, SMEM_A>>>(q, wo, part, HID, HID);
    reduce_res_norm<<<T, 256>>>(part, x, post_w, hidden, xn);
    // 4. act = silu(xn@Wg^T) * (xn@Wu^T)   (fused, fp16, padded N)
    gemm_gateup<<<gridF, 128, SMEM_F>>>(xn, wg, wu, act, HID);
    // 5. down partials = act @ Wd^T (split-K); out = hidden + p
    gemm_split<<<gridS, 128, SMEM_A>>>(act, wd, part, INTP, HID);
    reduce_res_out<<<rblk, 256>>>(part, hidden, out, n4h);
}

// round 15
// speedup vs baseline: 1.5215x; 1.0137x over previous
#include <cuda_runtime.h>
#include <cuda_fp16.h>
#include <cstdint>

#define HID   2048
#define INTER 10944
#define INTP  11008          // padded: 86*128, 172*64
#define TTOK  4096
#define EPS   1e-6f

#define BK 64                // fp16 elems per k-chunk = 128B swizzled row

// ---- split-K GEMM (q/o/down): BM=128, BN=128, 128 threads (2x2 warps, 64x64 tiles) ----
#define A_BY   (128*128)                 // 16 KB
#define B_BY   (128*128)                 // 16 KB
#define STAGE_A (A_BY + B_BY)            // 32 KB
#define SMEM_A (2*STAGE_A)               // 64 KB -> 3 CTAs/SM

// ---- fused gate/up: BM=128, BN=64 per weight ----
#define FA_BY  (128*128)                 // 16 KB
#define FB_BY  (64*128)                  // 8 KB each weight
#define STAGE_F (FA_BY + 2*FB_BY)        // 32 KB
#define SMEM_F (2*STAGE_F)               // 64 KB -> 3 CTAs/SM

// ---------------- scratch ----------------
__device__ __half g_part[2 * (size_t)TTOK * HID];   // split-K partials (fp16, 32 MB)
__device__ __half g_xn[(size_t)TTOK * HID];
__device__ __half g_q[(size_t)TTOK * HID];
__device__ float  g_hidden[(size_t)TTOK * HID];
__device__ __half g_act[(size_t)TTOK * INTP];
__device__ __half g_wq[(size_t)HID * HID];
__device__ __half g_wo[(size_t)HID * HID];
__device__ __half g_wg[(size_t)INTP * HID];
__device__ __half g_wu[(size_t)INTP * HID];
__device__ __half g_wd[(size_t)HID * INTP];

// ---------------- PTX helpers ----------------
__device__ __forceinline__ uint32_t smem_u32(const void* p) {
    uint32_t a;
    asm("{ .reg .u64 t; cvta.to.shared.u64 t, %1; cvt.u32.u64 %0, t; }" : "=r"(a) : "l"(p));
    return a;
}
#define SWZ(off) ((off) ^ (((off) >> 3) & 0x70))

__device__ __forceinline__ void cp16(uint32_t smem_dst, const void* gsrc) {
    asm volatile("cp.async.cg.shared.global [%0], [%1], 16;" :: "r"(smem_dst), "l"(gsrc));
}
#define CP_COMMIT  asm volatile("cp.async.commit_group;" ::: "memory")
#define CP_WAIT(n) asm volatile("cp.async.wait_group %0;" :: "n"(n) : "memory")

__device__ __forceinline__ void ldsm_x4(uint32_t r[4], uint32_t saddr) {
    asm volatile("ldmatrix.sync.aligned.m8n8.x4.shared.b16 {%0,%1,%2,%3}, [%4];"
        : "=r"(r[0]), "=r"(r[1]), "=r"(r[2]), "=r"(r[3]) : "r"(saddr));
}

__device__ __forceinline__ void mma16816(float c[4], const uint32_t a[4],
                                         uint32_t b0, uint32_t b1) {
    asm volatile(
        "mma.sync.aligned.m16n8k16.row.col.f32.f16.f16.f32 "
        "{%0,%1,%2,%3}, {%4,%5,%6,%7}, {%8,%9}, {%0,%1,%2,%3};"
        : "+f"(c[0]), "+f"(c[1]), "+f"(c[2]), "+f"(c[3])
        : "r"(a[0]), "r"(a[1]), "r"(a[2]), "r"(a[3]), "r"(b0), "r"(b1));
}

// ============ split-K GEMM: P[kz] = A[:, kz*K/2 : (kz+1)*K/2] @ B^T slice ============
// BM=128, BN=128, warps 2x2, warp tile 64x64, 3 CTAs/SM. blockIdx.z = kz (0/1).
// Writes fp16 partial to P + kz*M*N.
__global__ void __launch_bounds__(128, 3)
gemm_split(const __half* __restrict__ A, const __half* __restrict__ B,
           __half* __restrict__ P, int K, int N) {
    extern __shared__ char smem[];
    const uint32_t sb = smem_u32(smem);
    const int tid = threadIdx.x, warp = tid >> 5, lane = tid & 31;
    const int wm = warp & 1, wn = warp >> 1;
    const int m0 = blockIdx.x * 128, n0 = blockIdx.y * 128;
    const int kz = blockIdx.z;
    const int Kh = K >> 1;
    const int nkb = Kh / BK;
    __half* Cf = P + (size_t)kz * ((size_t)gridDim.x * 128) * N;

    const __half* Ag = A + (size_t)m0 * K + (size_t)kz * Kh;
    const __half* Bg = B + (size_t)n0 * K + (size_t)kz * Kh;
    auto issue = [&](int kb) {
        const uint32_t base = sb + (kb & 1) * STAGE_A;
        const int koff = kb * BK;
        #pragma unroll
        for (int i = 0; i < 16; i++) {
            const int c = tid + i * 128;
            const int idx = c & 1023, r = idx >> 3, cc = idx & 7;
            const uint32_t so = SWZ((uint32_t)(r * 128 + cc * 16));
            const size_t go = (size_t)r * K + koff + cc * 8;
            if (c < 1024) cp16(base + so,         Ag + go);
            else          cp16(base + A_BY + so,  Bg + go);
        }
    };

    const int frow = (lane & 7) | (((lane >> 3) & 1) << 3);
    const int fg = lane >> 4, fx = frow & 7;
    uint32_t arow[4], brow[4];
    #pragma unroll
    for (int mi = 0; mi < 4; mi++) arow[mi] = (uint32_t)((wm * 64 + mi * 16 + frow) * 128);
    #pragma unroll
    for (int nj = 0; nj < 4; nj++) brow[nj] = (uint32_t)(A_BY + (wn * 64 + nj * 16 + frow) * 128);

    float acc[4][8][4];
    #pragma unroll
    for (int mi = 0; mi < 4; mi++)
        #pragma unroll
        for (int j = 0; j < 8; j++)
            #pragma unroll
            for (int r = 0; r < 4; r++) acc[mi][j][r] = 0.0f;

    issue(0); CP_COMMIT;

    for (int kb = 0; kb < nkb; ++kb) {
        if (kb + 1 < nkb) { issue(kb + 1); CP_COMMIT; CP_WAIT(1); }
        else              { CP_WAIT(0); }
        __syncthreads();

        const uint32_t base = sb + (kb & 1) * STAGE_A;
        #pragma unroll
        for (int ks = 0; ks < 4; ks++) {
            const uint32_t colx = (uint32_t)(((2 * ks + fg) ^ fx) << 4);
            uint32_t a[4][4], b[4][4];
            #pragma unroll
            for (int mi = 0; mi < 4; mi++) ldsm_x4(a[mi], base + arow[mi] + colx);
            #pragma unroll
            for (int nj = 0; nj < 4; nj++) ldsm_x4(b[nj], base + brow[nj] + colx);
            #pragma unroll
            for (int mi = 0; mi < 4; mi++)
                #pragma unroll
                for (int nj = 0; nj < 4; nj++) {
                    mma16816(acc[mi][2 * nj + 0], a[mi], b[nj][0], b[nj][2]);
                    mma16816(acc[mi][2 * nj + 1], a[mi], b[nj][1], b[nj][3]);
                }
        }
        __syncthreads();   // 2-stage ring
    }

    const int rb = m0 + wm * 64 + (lane >> 2);
    const int cb = n0 + wn * 64 + (lane & 3) * 2;
    #pragma unroll
    for (int mi = 0; mi < 4; mi++) {
        #pragma unroll
        for (int j = 0; j < 8; j++) {
            const int r0 = rb + mi * 16;
            const int c  = cb + j * 8;
            *(__half2*)(Cf + (size_t)r0 * N + c) =
                __floats2half2_rn(acc[mi][j][0], acc[mi][j][1]);
            *(__half2*)(Cf + (size_t)(r0 + 8) * N + c) =
                __floats2half2_rn(acc[mi][j][2], acc[mi][j][3]);
        }
    }
}

// ======= fused gate/up + silu.  act = silu(A@Wg^T) * (A@Wu^T) =======
__global__ void __launch_bounds__(128, 3)
gemm_gateup(const __half* __restrict__ A, const __half* __restrict__ Wg,
            const __half* __restrict__ Wu, __half* __restrict__ act, int K) {
    extern __shared__ char smem[];
    const uint32_t sb = smem_u32(smem);
    const int tid = threadIdx.x, warp = tid >> 5, lane = tid & 31;
    const int wm = warp & 1, wn = warp >> 1;
    const int m0 = blockIdx.x * 128, n0 = blockIdx.y * 64;
    const int nkb = K / BK;

    const __half* Ag = A  + (size_t)m0 * K;
    const __half* Gg = Wg + (size_t)n0 * K;
    const __half* Ug = Wu + (size_t)n0 * K;
    auto issue = [&](int kb) {
        const uint32_t base = sb + (kb & 1) * STAGE_F;
        const int koff = kb * BK;
        #pragma unroll
        for (int i = 0; i < 16; i++) {
            const int c = tid + i * 128;
            if (c < 1024) {
                const int r = c >> 3, cc = c & 7;
                cp16(base + SWZ((uint32_t)(r * 128 + cc * 16)),
                     Ag + (size_t)r * K + koff + cc * 8);
            } else if (c < 1536) {
                const int idx = c - 1024, r = idx >> 3, cc = idx & 7;
                cp16(base + FA_BY + SWZ((uint32_t)(r * 128 + cc * 16)),
                     Gg + (size_t)r * K + koff + cc * 8);
            } else {
                const int idx = c - 1536, r = idx >> 3, cc = idx & 7;
                cp16(base + FA_BY + FB_BY + SWZ((uint32_t)(r * 128 + cc * 16)),
                     Ug + (size_t)r * K + koff + cc * 8);
            }
        }
    };

    const int frow = (lane & 7) | (((lane >> 3) & 1) << 3);
    const int fg = lane >> 4, fx = frow & 7;
    uint32_t arow[4], grow[2], urow[2];
    #pragma unroll
    for (int mi = 0; mi < 4; mi++) arow[mi] = (uint32_t)((wm * 64 + mi * 16 + frow) * 128);
    #pragma unroll
    for (int nj = 0; nj < 2; nj++) {
        grow[nj] = (uint32_t)(FA_BY         + (wn * 32 + nj * 16 + frow) * 128);
        urow[nj] = (uint32_t)(FA_BY + FB_BY + (wn * 32 + nj * 16 + frow) * 128);
    }

    float ag[4][4][4], au[4][4][4];
    #pragma unroll
    for (int mi = 0; mi < 4; mi++)
        #pragma unroll
        for (int j = 0; j < 4; j++)
            #pragma unroll
            for (int r = 0; r < 4; r++) { ag[mi][j][r] = 0.0f; au[mi][j][r] = 0.0f; }

    issue(0); CP_COMMIT;

    for (int kb = 0; kb < nkb; ++kb) {
        if (kb + 1 < nkb) { issue(kb + 1); CP_COMMIT; CP_WAIT(1); }
        else              { CP_WAIT(0); }
        __syncthreads();

        const uint32_t base = sb + (kb & 1) * STAGE_F;
        #pragma unroll
        for (int ks = 0; ks < 4; ks++) {
            const uint32_t colx = (uint32_t)(((2 * ks + fg) ^ fx) << 4);
            uint32_t a[4][4], bg[2][4], bu[2][4];
            #pragma unroll
            for (int mi = 0; mi < 4; mi++) ldsm_x4(a[mi], base + arow[mi] + colx);
            #pragma unroll
            for (int nj = 0; nj < 2; nj++) {
                ldsm_x4(bg[nj], base + grow[nj] + colx);
                ldsm_x4(bu[nj], base + urow[nj] + colx);
            }
            #pragma unroll
            for (int mi = 0; mi < 4; mi++)
                #pragma unroll
                for (int nj = 0; nj < 2; nj++) {
                    mma16816(ag[mi][2 * nj + 0], a[mi], bg[nj][0], bg[nj][2]);
                    mma16816(ag[mi][2 * nj + 1], a[mi], bg[nj][1], bg[nj][3]);
                    mma16816(au[mi][2 * nj + 0], a[mi], bu[nj][0], bu[nj][2]);
                    mma16816(au[mi][2 * nj + 1], a[mi], bu[nj][1], bu[nj][3]);
                }
        }
        __syncthreads();
    }

    const int rb = m0 + wm * 64 + (lane >> 2);
    const int cb = n0 + wn * 32 + (lane & 3) * 2;
    #pragma unroll
    for (int mi = 0; mi < 4; mi++) {
        #pragma unroll
        for (int j = 0; j < 4; j++) {
            const int r0 = rb + mi * 16;
            const int c  = cb + j * 8;
            float g0 = ag[mi][j][0], g1 = ag[mi][j][1], g2 = ag[mi][j][2], g3 = ag[mi][j][3];
            float v0 = g0 / (1.0f + __expf(-g0)) * au[mi][j][0];
            float v1 = g1 / (1.0f + __expf(-g1)) * au[mi][j][1];
            float v2 = g2 / (1.0f + __expf(-g2)) * au[mi][j][2];
            float v3 = g3 / (1.0f + __expf(-g3)) * au[mi][j][3];
            *(__half2*)(act + (size_t)r0 * INTP + c)       = __floats2half2_rn(v0, v1);
            *(__half2*)(act + (size_t)(r0 + 8) * INTP + c) = __floats2half2_rn(v2, v3);
        }
    }
}

// ---------------- reduce kernels (deterministic fixed-order sums) ----------------
__device__ __forceinline__ float2 h2f(uint32_t h) { return __half22float2(*(__half2*)&h); }

// q = fp16(p0 + p1)   (8 halves per thread)
__global__ void reduce_q(const __half* __restrict__ p, __half* __restrict__ q, size_t n8) {
    const size_t i = (size_t)blockIdx.x * blockDim.x + threadIdx.x;
    if (i >= n8) return;
    uint4 a = ((const uint4*)p)[i];
    uint4 b = ((const uint4*)(p + (size_t)TTOK * HID))[i];
    uint4 o;
    uint32_t* ap = (uint32_t*)&a; uint32_t* bp = (uint32_t*)&b; uint32_t* op = (uint32_t*)&o;
    #pragma unroll
    for (int j = 0; j < 4; j++) {
        float2 fa = h2f(ap[j]), fb = h2f(bp[j]);
        __half2 r = __floats2half2_rn(fa.x + fb.x, fa.y + fb.y);
        op[j] = *(uint32_t*)&r;
    }
    ((uint4*)q)[i] = o;
}

// hidden = x + p0 + p1;  xn = fp16(rmsnorm(hidden) * w)   (fused o-reduce + post-LN)
__global__ void reduce_res_norm(const __half* __restrict__ p, const float* __restrict__ x,
                                const float* __restrict__ w, float* __restrict__ hidden,
                                __half* __restrict__ xn) {
    const int row = blockIdx.x, t = threadIdx.x;   // 256 threads x 8 elems
    const size_t off = (size_t)row * HID;
    const float4* xv = (const float4*)(x + off);
    float4 h0 = xv[2 * t], h1 = xv[2 * t + 1];
    {
        uint4 pa = ((const uint4*)(p + off))[t];
        uint4 pb = ((const uint4*)(p + (size_t)TTOK * HID + off))[t];
        uint32_t* ap = (uint32_t*)&pa; uint32_t* bp = (uint32_t*)&pb;
        float2 a0 = h2f(ap[0]), a1 = h2f(ap[1]), a2 = h2f(ap[2]), a3 = h2f(ap[3]);
        float2 b0 = h2f(bp[0]), b1 = h2f(bp[1]), b2 = h2f(bp[2]), b3 = h2f(bp[3]);
        h0.x += a0.x + b0.x; h0.y += a0.y + b0.y; h0.z += a1.x + b1.x; h0.w += a1.y + b1.y;
        h1.x += a2.x + b2.x; h1.y += a2.y + b2.y; h1.z += a3.x + b3.x; h1.w += a3.y + b3.y;
    }
    float4* hv = (float4*)(hidden + off);
    hv[2 * t] = h0; hv[2 * t + 1] = h1;

    float ss = h0.x*h0.x + h0.y*h0.y + h0.z*h0.z + h0.w*h0.w
             + h1.x*h1.x + h1.y*h1.y + h1.z*h1.z + h1.w*h1.w;
    __shared__ float red[8];
    #pragma unroll
    for (int o = 16; o; o >>= 1) ss += __shfl_xor_sync(0xffffffffu, ss, o);
    if ((t & 31) == 0) red[t >> 5] = ss;
    __syncthreads();
    float tot = red[0]+red[1]+red[2]+red[3]+red[4]+red[5]+red[6]+red[7];
    const float sc = rsqrtf(tot * (1.0f / HID) + EPS);
    const float4* wv = (const float4*)w;
    float4 wa = wv[2 * t], wb = wv[2 * t + 1];
    uint4 o;
    uint32_t* op = (uint32_t*)&o;
    __half2 t0 = __floats2half2_rn(h0.x*sc*wa.x, h0.y*sc*wa.y); op[0] = *(uint32_t*)&t0;
    __half2 t1 = __floats2half2_rn(h0.z*sc*wa.z, h0.w*sc*wa.w); op[1] = *(uint32_t*)&t1;
    __half2 t2 = __floats2half2_rn(h1.x*sc*wb.x, h1.y*sc*wb.y); op[2] = *(uint32_t*)&t2;
    __half2 t3 = __floats2half2_rn(h1.z*sc*wb.z, h1.w*sc*wb.w); op[3] = *(uint32_t*)&t3;
    ((uint4*)(xn + off))[t] = o;
}

// out = hidden + p0 + p1   (8 elems per thread)
__global__ void reduce_res_out(const __half* __restrict__ p, const float* __restrict__ hidden,
                               float* __restrict__ out, size_t n8) {
    const size_t i = (size_t)blockIdx.x * blockDim.x + threadIdx.x;
    if (i >= n8) return;
    float4 h0 = ((const float4*)hidden)[2 * i];
    float4 h1 = ((const float4*)hidden)[2 * i + 1];
    uint4 pa = ((const uint4*)p)[i];
    uint4 pb = ((const uint4*)(p + (size_t)TTOK * HID))[i];
    uint32_t* ap = (uint32_t*)&pa; uint32_t* bp = (uint32_t*)&pb;
    float2 a0 = h2f(ap[0]), a1 = h2f(ap[1]), a2 = h2f(ap[2]), a3 = h2f(ap[3]);
    float2 b0 = h2f(bp[0]), b1 = h2f(bp[1]), b2 = h2f(bp[2]), b3 = h2f(bp[3]);
    h0.x += a0.x + b0.x; h0.y += a0.y + b0.y; h0.z += a1.x + b1.x; h0.w += a1.y + b1.y;
    h1.x += a2.x + b2.x; h1.y += a2.y + b2.y; h1.z += a3.x + b3.x; h1.w += a3.y + b3.y;
    ((float4*)out)[2 * i]     = h0;
    ((float4*)out)[2 * i + 1] = h1;
}

// ---------------- fp32 -> fp16 weight convert, divide-free 2D grid ----------------
// row = blockIdx.y; each thread converts 8 contiguous cols. Pads with zeros.
__global__ void cvt_pad2(const float* __restrict__ in, __half* __restrict__ out,
                         int co, int ri, int ci) {
    const int r = blockIdx.y;
    const int c = (blockIdx.x * blockDim.x + threadIdx.x) * 8;
    if (c >= co) return;
    uint4 h = make_uint4(0, 0, 0, 0);     // half 0.0 = bit pattern 0
    if (r < ri && c < ci) {
        const float4* src = (const float4*)(in + (size_t)r * ci + c);
        float4 v0 = src[0], v1 = src[1];
        uint32_t* hp = (uint32_t*)&h;
        __half2 a0 = __floats2half2_rn(v0.x, v0.y); hp[0] = *(uint32_t*)&a0;
        __half2 a1 = __floats2half2_rn(v0.z, v0.w); hp[1] = *(uint32_t*)&a1;
        __half2 a2 = __floats2half2_rn(v1.x, v1.y); hp[2] = *(uint32_t*)&a2;
        __half2 a3 = __floats2half2_rn(v1.z, v1.w); hp[3] = *(uint32_t*)&a3;
    }
    *(uint4*)(out + (size_t)r * co + c) = h;
}

// ---------------- rmsnorm -> fp16 ----------------
__global__ void rmsnorm_h(const float* __restrict__ x, const float* __restrict__ w,
                          __half* __restrict__ out) {
    const int row = blockIdx.x, t = threadIdx.x;
    const float4* xv = (const float4*)(x + (size_t)row * HID);
    const float4* wv = (const float4*)w;
    float4 a = xv[t], b = xv[t + 256];
    float ss = a.x*a.x + a.y*a.y + a.z*a.z + a.w*a.w
             + b.x*b.x + b.y*b.y + b.z*b.z + b.w*b.w;
    __shared__ float red[8];
    #pragma unroll
    for (int o = 16; o; o >>= 1) ss += __shfl_xor_sync(0xffffffffu, ss, o);
    if ((t & 31) == 0) red[t >> 5] = ss;
    __syncthreads();
    float tot = red[0]+red[1]+red[2]+red[3]+red[4]+red[5]+red[6]+red[7];
    const float sc = rsqrtf(tot * (1.0f / HID) + EPS);
    float4 wa = wv[t], wb = wv[t + 256];
    __half2* ov = (__half2*)(out + (size_t)row * HID);
    ov[2*t]   = __floats2half2_rn(a.x*sc*wa.x, a.y*sc*wa.y);
    ov[2*t+1] = __floats2half2_rn(a.z*sc*wa.z, a.w*sc*wa.w);
    ov[2*(t+256)]   = __floats2half2_rn(b.x*sc*wb.x, b.y*sc*wb.y);
    ov[2*(t+256)+1] = __floats2half2_rn(b.z*sc*wb.z, b.w*sc*wb.w);
}

// ---------------- launcher ----------------
extern "C" void kernel_launch(void* const* d_in, const int* in_sizes, int n_in,
                              void* d_out, int out_size) {
    const float* x      = (const float*)d_in[0];
    const float* in_w   = (const float*)d_in[2];
    const float* post_w = (const float*)d_in[3];
    const float* Wq     = (const float*)d_in[4];
    const float* Wo     = (const float*)d_in[5];
    const float* Wg     = (const float*)d_in[6];
    const float* Wu     = (const float*)d_in[7];
    const float* Wd     = (const float*)d_in[8];
    float* out = (float*)d_out;
    const int T = in_sizes[0] / HID;  // 4096

    __half *xn, *q, *act, *part, *wq, *wo, *wg, *wu, *wd;
    float* hidden;
    cudaGetSymbolAddress((void**)&xn, g_xn);
    cudaGetSymbolAddress((void**)&q, g_q);
    cudaGetSymbolAddress((void**)&hidden, g_hidden);
    cudaGetSymbolAddress((void**)&act, g_act);
    cudaGetSymbolAddress((void**)&part, g_part);
    cudaGetSymbolAddress((void**)&wq, g_wq);
    cudaGetSymbolAddress((void**)&wo, g_wo);
    cudaGetSymbolAddress((void**)&wg, g_wg);
    cudaGetSymbolAddress((void**)&wu, g_wu);
    cudaGetSymbolAddress((void**)&wd, g_wd);

    cudaFuncSetAttribute(gemm_split, cudaFuncAttributeMaxDynamicSharedMemorySize, SMEM_A);
    cudaFuncSetAttribute(gemm_gateup, cudaFuncAttributeMaxDynamicSharedMemorySize, SMEM_F);

    // weight conversion (fp32 -> fp16, padded for INTER), divide-free 2D grids
    {
        auto launch_cvt = [&](const float* src, __half* dst, int ro, int co, int ri, int ci) {
            dim3 grid((unsigned)((co / 8 + 255) / 256), (unsigned)ro);
            cvt_pad2<<<grid, 256>>>(src, dst, co, ri, ci);
        };
        launch_cvt(Wq, wq, HID, HID, HID, HID);
        launch_cvt(Wo, wo, HID, HID, HID, HID);
        launch_cvt(Wg, wg, INTP, HID, INTER, HID);
        launch_cvt(Wu, wu, INTP, HID, INTER, HID);
        launch_cvt(Wd, wd, HID, INTP, HID, INTER);
    }

    const dim3 gridS(T / 128, HID / 128, 2);   // (32, 16, 2) = 1024 CTAs
    const dim3 gridF(T / 128, INTP / 64);      // (32, 172)
    const size_t n8h = (size_t)T * HID / 8;
    const unsigned rblk = (unsigned)((n8h + 255) / 256);

    // 1. input_layernorm -> fp16
    rmsnorm_h<<<T, 256>>>(x, in_w, xn);
    // 2. q partials = xn @ Wq^T (split-K), then q = fp16(p0+p1)
    gemm_split<<<gridS, 128, SMEM_A>>>(xn, wq, part, HID, HID);
    reduce_q<<<rblk, 256>>>(part, q, n8h);
    // 3. o partials = q @ Wo^T (split-K); hidden = x + p; xn = postLN(hidden)
    gemm_split<<<gridS, 128, SMEM_A>>>(q, wo, part, HID, HID);
    reduce_res_norm<<<T, 256>>>(part, x, post_w, hidden, xn);
    // 4. act = silu(xn@Wg^T) * (xn@Wu^T)   (fused, fp16, padded N)
    gemm_gateup<<<gridF, 128, SMEM_F>>>(xn, wg, wu, act, HID);
    // 5. down partials = act @ Wd^T (split-K); out = hidden + p
    gemm_split<<<gridS, 128, SMEM_A>>>(act, wd, part, INTP, HID);
    reduce_res_out<<<rblk, 256>>>(part, hidden, out, n8h);
}